// round 7
// baseline (speedup 1.0000x reference)
#include <cuda_runtime.h>
#include <cuda_fp16.h>
#include <math.h>
#include <stdint.h>

// ============================================================================
// ConvolutionKAN as mma.sync fp16 GEMM (sm_100-safe, fp32 accumulate):
//   out[61504,128] = A[61504,2592] @ W[2592,128] + bias
//   K layout: k in [0,2304): spline (i=k>>3, c=k&7, uniform cubic B-spline
//             closed form); k in [2304,2592): silu(x_i).
// R7: fp16 operands (same mantissa as tf32), m16n8k16, ldmatrix.x4 A-frags,
//     cp.async W staging, A row stride 80 B (LDSM conflict-free).
// ============================================================================

#define N_TOTAL   61504
#define K_TOTAL   2592
#define FILTERS   128
#define BM        128
#define NKT       81
#define NSPLINE   72

#define A_STAGE_B  10240               // 128 rows * 80 B
#define W_STAGE_B  8192                // 32k * 128o * 2B (frag-ordered)
#define SMEM_A_OFF 0
#define SMEM_W_OFF (2 * A_STAGE_B)     // 20480
#define SMEM_TOTAL (2 * A_STAGE_B + 2 * W_STAGE_B)   // 36864 B

// W in m16n8k16 B-fragment word order per 32-k tile:
//   word = ks*1024 + ob*64 + lane*2 + r   (uint32 = 2 halfs)
//   halfs: k = kt*32 + ks*16 + 2*(lane&3) + 8*r + hh,  o = ob*8 + (lane>>2)
__device__ __half g_Wh[K_TOTAL * FILTERS];

// ---------------------------------------------------------------- helpers --
__device__ __forceinline__ uint32_t pack2(float a, float b) {
    __half2 h = __floats2half2_rn(a, b);
    return *reinterpret_cast<uint32_t*>(&h);
}
__device__ __forceinline__ void sts16(uint32_t addr, uint32_t a, uint32_t b,
                                      uint32_t c, uint32_t d) {
    asm volatile("st.shared.v4.b32 [%0], {%1,%2,%3,%4};"
                 :: "r"(addr), "r"(a), "r"(b), "r"(c), "r"(d) : "memory");
}
__device__ __forceinline__ void lds_v2(uint32_t addr, uint32_t& a, uint32_t& b) {
    asm volatile("ld.shared.v2.b32 {%0,%1}, [%2];" : "=r"(a), "=r"(b) : "r"(addr));
}
__device__ __forceinline__ void ldsm4(uint32_t addr, uint32_t* r) {
    asm volatile("ldmatrix.sync.aligned.m8n8.x4.shared.b16 {%0,%1,%2,%3}, [%4];"
                 : "=r"(r[0]), "=r"(r[1]), "=r"(r[2]), "=r"(r[3]) : "r"(addr));
}
__device__ __forceinline__ void mma16(float* d, const uint32_t* a,
                                      uint32_t b0, uint32_t b1) {
    asm volatile(
        "mma.sync.aligned.m16n8k16.row.col.f32.f16.f16.f32 "
        "{%0,%1,%2,%3}, {%4,%5,%6,%7}, {%8,%9}, {%0,%1,%2,%3};"
        : "+f"(d[0]), "+f"(d[1]), "+f"(d[2]), "+f"(d[3])
        : "r"(a[0]), "r"(a[1]), "r"(a[2]), "r"(a[3]), "r"(b0), "r"(b1));
}
__device__ __forceinline__ void cpasync16(uint32_t saddr, const void* gptr) {
    asm volatile("cp.async.cg.shared.global [%0], [%1], 16;"
                 :: "r"(saddr), "l"(__cvta_generic_to_global(gptr)) : "memory");
}

// --------------------------------------------------------- weight fuse -----
__global__ void fuse_weights(const float* __restrict__ sk,   // [288,8,128]
                             const float* __restrict__ sc) { // [288,128]
    int w = blockIdx.x * 256 + threadIdx.x;                  // uint32 words
    if (w >= K_TOTAL * FILTERS / 2) return;
    int kt   = w >> 11;                 // 2048 words per 32-k tile
    int rem  = w & 2047;
    int ks   = rem >> 10;
    int rem2 = rem & 1023;
    int ob   = rem2 >> 6;
    int l2   = rem2 & 63;
    int l    = l2 >> 1;
    int r    = l2 & 1;
    int o    = ob * 8 + (l >> 2);
    int kb   = kt * 32 + ks * 16 + 2 * (l & 3) + 8 * r;
    float v[2];
#pragma unroll
    for (int hh = 0; hh < 2; ++hh) {
        int k = kb + hh;
        if (k < 2304) {
            int i = k >> 3;
            v[hh] = sk[k * 128 + o] * sc[i * 128 + o];
        } else {
            v[hh] = sc[(k - 2304) * 128 + o];
        }
    }
    ((uint32_t*)g_Wh)[w] = pack2(v[0], v[1]);
}

// ------------------------------------------------------------ A builder ----
// Thread builds HALF of one row's 32-k slice (16 halfs = 32 B = 2 st.v4).
__device__ __forceinline__ void build_a_half(int kt, int h, uint32_t dst,
                                             const float* __restrict__ rowbase) {
    if (kt < NSPLINE) {
        int i0  = kt * 4;
        int di  = i0 / 96;
        int rem = i0 - di * 96;
        int dj  = rem >> 5;
        int c0  = rem & 31;
        float2 xv = *reinterpret_cast<const float2*>(
            rowbase + (di * 64 + dj) * 32 + c0 + 2 * h);
        float xs[2] = {xv.x, xv.y};
#pragma unroll
        for (int g = 0; g < 2; ++g) {
            float x  = xs[g];
            float tp = (x + 1.0f) * 2.5f;            // uniform grid, h = 0.4
            int j = (int)floorf(tp);
            j = max(0, min(4, j));
            float u  = tp - (float)j;
            float um = 1.0f - u;
            float u2 = u * u, u3 = u2 * u;
            float b0 = um * um * um * (1.0f / 6.0f);
            float b1 = (3.0f * u3 - 6.0f * u2 + 4.0f) * (1.0f / 6.0f);
            float b2 = (-3.0f * u3 + 3.0f * u2 + 3.0f * u + 1.0f) * (1.0f / 6.0f);
            float b3 = u3 * (1.0f / 6.0f);
            float f[8];
#pragma unroll
            for (int z = 0; z < 8; ++z) f[z] = 0.f;
            f[j]     = b0;
            f[j + 1] = b1;
            f[j + 2] = b2;
            f[j + 3] = b3;
            sts16(dst + g * 16,
                  pack2(f[0], f[1]), pack2(f[2], f[3]),
                  pack2(f[4], f[5]), pack2(f[6], f[7]));
        }
    } else {
        int ib = kt - NSPLINE;
        int di = ib / 3;
        int dj = ib - di * 3;
        const float* src = rowbase + (di * 64 + dj) * 32 + h * 16;
#pragma unroll
        for (int q = 0; q < 2; ++q) {
            float4 x0 = *reinterpret_cast<const float4*>(src + q * 8);
            float4 x1 = *reinterpret_cast<const float4*>(src + q * 8 + 4);
            float f[8] = {x0.x, x0.y, x0.z, x0.w, x1.x, x1.y, x1.z, x1.w};
            uint32_t p[4];
#pragma unroll
            for (int z = 0; z < 4; ++z) {
                float a = f[2 * z],     sa = a / (1.0f + __expf(-a));
                float b = f[2 * z + 1], sb = b / (1.0f + __expf(-b));
                p[z] = pack2(sa, sb);
            }
            sts16(dst + q * 16, p[0], p[1], p[2], p[3]);
        }
    }
}

// -------------------------------------------------------------- main -------
__global__ __launch_bounds__(256, 2)
void kan_mma_kernel(const float* __restrict__ input,   // [16,64,64,32]
                    const float* __restrict__ bias,    // [128]
                    float* __restrict__ out) {         // [61504,128]
    extern __shared__ char smem[];
    const uint32_t sb = (uint32_t)__cvta_generic_to_shared(smem);
    const uint32_t Ab = sb + SMEM_A_OFF;
    const uint32_t Wb = sb + SMEM_W_OFF;

    const int tid = threadIdx.x;
    const int l   = tid & 31;
    const int wid = tid >> 5;
    const int wm  = wid >> 1;          // 0..3 : M warp row (32 rows)
    const int wn  = wid & 1;           // 0..1 : N warp col (64 cols)

    // builder role: row = tid&127, k-half = tid>>7
    const int br = tid & 127;
    const int bh = tid >> 7;
    int n = blockIdx.x * BM + br;
    if (n >= N_TOTAL) n = N_TOTAL - 1;
    int bb = n / 3844;                  // 62*62
    int rr = n - bb * 3844;
    int yy = rr / 62;
    int xx = rr - yy * 62;
    const float* rowbase = input + ((bb * 64 + yy) * 64 + xx) * 32;
    const uint32_t adst = Ab + (uint32_t)br * 80 + (uint32_t)bh * 32;

    // ldmatrix address pieces (fixed per thread)
    const uint32_t arow_sel = (uint32_t)(wm * 32 + (l & 7) + ((l >> 3) & 1) * 8);
    const uint32_t acol_off = (uint32_t)((l >> 4) * 16);
    const uint32_t wfrag_off = (uint32_t)(l * 8);

    // accumulators initialized with bias
    float acc[2][8][4];
#pragma unroll
    for (int nf = 0; nf < 8; ++nf) {
        int o = wn * 64 + nf * 8 + (l & 3) * 2;
        float b0 = bias[o];
        float b1 = bias[o + 1];
#pragma unroll
        for (int mf = 0; mf < 2; ++mf) {
            acc[mf][nf][0] = b0;
            acc[mf][nf][1] = b1;
            acc[mf][nf][2] = b0;
            acc[mf][nf][3] = b1;
        }
    }

    // prologue: stage 0
    {
        const char* wsrc = (const char*)g_Wh;
#pragma unroll
        for (int v = 0; v < 2; ++v)
            cpasync16(Wb + v * 4096 + tid * 16, wsrc + v * 4096 + tid * 16);
        asm volatile("cp.async.commit_group;" ::: "memory");
        build_a_half(0, bh, adst, rowbase);
        asm volatile("cp.async.wait_group 0;" ::: "memory");
    }
    __syncthreads();

    for (int kt = 0; kt < NKT; ++kt) {
        const int s = kt & 1;

        // ---- stage next tile into the other buffers ----
        if (kt + 1 < NKT) {
            const char* wsrc = (const char*)g_Wh + (size_t)(kt + 1) * W_STAGE_B;
            const uint32_t wdst = Wb + (s ^ 1) * W_STAGE_B;
#pragma unroll
            for (int v = 0; v < 2; ++v)
                cpasync16(wdst + v * 4096 + tid * 16, wsrc + v * 4096 + tid * 16);
            asm volatile("cp.async.commit_group;" ::: "memory");
            build_a_half(kt + 1, bh, adst + (s ^ 1) * A_STAGE_B, rowbase);
        }

        // ---- compute current tile: warp 32(M) x 64(N), k=32 (2 x k16) ----
        const uint32_t As = Ab + s * A_STAGE_B;
        const uint32_t Ws = Wb + s * W_STAGE_B;
#pragma unroll
        for (int ks = 0; ks < 2; ++ks) {
            uint32_t a[2][4];
#pragma unroll
            for (int mf = 0; mf < 2; ++mf)
                ldsm4(As + (arow_sel + mf * 16) * 80 + ks * 32 + acol_off, a[mf]);
#pragma unroll
            for (int nf = 0; nf < 8; ++nf) {
                uint32_t b0, b1;
                lds_v2(Ws + ks * 4096 + (wn * 8 + nf) * 256 + wfrag_off, b0, b1);
#pragma unroll
                for (int mf = 0; mf < 2; ++mf)
                    mma16(acc[mf][nf], a[mf], b0, b1);
            }
        }
        asm volatile("cp.async.wait_group 0;" ::: "memory");
        __syncthreads();
    }

    // ---- epilogue: direct float2 stores (bias already folded) ----
#pragma unroll
    for (int mf = 0; mf < 2; ++mf) {
        int r0 = blockIdx.x * BM + wm * 32 + mf * 16 + (l >> 2);
#pragma unroll
        for (int nf = 0; nf < 8; ++nf) {
            int o = wn * 64 + nf * 8 + (l & 3) * 2;
            if (r0 < N_TOTAL) {
                float2 v = make_float2(acc[mf][nf][0], acc[mf][nf][1]);
                *reinterpret_cast<float2*>(out + (size_t)r0 * FILTERS + o) = v;
            }
            if (r0 + 8 < N_TOTAL) {
                float2 v = make_float2(acc[mf][nf][2], acc[mf][nf][3]);
                *reinterpret_cast<float2*>(out + (size_t)(r0 + 8) * FILTERS + o) = v;
            }
        }
    }
}

// ------------------------------------------------------------- launcher ----
extern "C" void kernel_launch(void* const* d_in, const int* in_sizes, int n_in,
                              void* d_out, int out_size) {
    const float* input = (const float*)d_in[0];   // (16,64,64,32)
    const float* sk    = (const float*)d_in[1];   // (288,8,128)
    const float* sc    = (const float*)d_in[2];   // (288,128)
    const float* bias  = (const float*)d_in[3];   // (128,)
    float* out = (float*)d_out;
    (void)in_sizes; (void)n_in; (void)out_size;

    static bool attr_done = false;
    if (!attr_done) {
        cudaFuncSetAttribute(kan_mma_kernel,
                             cudaFuncAttributeMaxDynamicSharedMemorySize, SMEM_TOTAL);
        attr_done = true;
    }

    int wwords = K_TOTAL * FILTERS / 2;
    fuse_weights<<<(wwords + 255) / 256, 256>>>(sk, sc);

    int blocks = (N_TOTAL + BM - 1) / BM;   // 481
    kan_mma_kernel<<<blocks, 256, SMEM_TOTAL>>>(input, bias, out);
}